// round 17
// baseline (speedup 1.0000x reference)
#include <cuda_runtime.h>
#include <cuda_fp16.h>
#include <cstdint>

#define NG   4
#define NB   4
#define LQ   512
#define NC   768
#define NH   12
#define DH   64
#define MPG  (NB*LQ)           // 2048 rows per group

// Half scratch (uint4 arrays force 16B alignment).
__device__ uint4 g_qh[NG*NB*NH*LQ*DH/8];
__device__ uint4 g_kh[NG*NB*NH*LQ*DH/8];
__device__ uint4 g_vh[NG*NB*NH*LQ*DH/8];
// hs as half: [g][2048][768]
__device__ uint4 g_hsh[NG*MPG*NC/8];
// Weights as half, ORIGINAL [k][n] layout: [which*4+g][768][768]
__device__ uint4 g_wh[12*NC*NC/8];

__device__ __forceinline__ void mma_f16(float* d, const uint32_t* a, const uint32_t* b) {
    asm volatile(
        "mma.sync.aligned.m16n8k16.row.col.f32.f16.f16.f32 "
        "{%0,%1,%2,%3}, {%4,%5,%6,%7}, {%8,%9}, {%0,%1,%2,%3};"
        : "+f"(d[0]), "+f"(d[1]), "+f"(d[2]), "+f"(d[3])
        : "r"(a[0]), "r"(a[1]), "r"(a[2]), "r"(a[3]), "r"(b[0]), "r"(b[1]));
}

__device__ __forceinline__ void ldmx2t(uint32_t& b0, uint32_t& b1, uint32_t saddr) {
    asm volatile("ldmatrix.sync.aligned.m8n8.x2.trans.shared.b16 {%0,%1}, [%2];"
                 : "=r"(b0), "=r"(b1) : "r"(saddr));
}
__device__ __forceinline__ void ldmx2(uint32_t& b0, uint32_t& b1, uint32_t saddr) {
    asm volatile("ldmatrix.sync.aligned.m8n8.x2.shared.b16 {%0,%1}, [%2];"
                 : "=r"(b0), "=r"(b1) : "r"(saddr));
}
__device__ __forceinline__ void ldmx4(uint32_t* d, uint32_t saddr) {
    asm volatile("ldmatrix.sync.aligned.m8n8.x4.shared.b16 {%0,%1,%2,%3}, [%4];"
                 : "=r"(d[0]), "=r"(d[1]), "=r"(d[2]), "=r"(d[3]) : "r"(saddr));
}
__device__ __forceinline__ void ldmx4t(uint32_t* d, uint32_t saddr) {
    asm volatile("ldmatrix.sync.aligned.m8n8.x4.trans.shared.b16 {%0,%1,%2,%3}, [%4];"
                 : "=r"(d[0]), "=r"(d[1]), "=r"(d[2]), "=r"(d[3]) : "r"(saddr));
}

__device__ __forceinline__ uint32_t cvta_s(const void* p) {
    return (uint32_t)__cvta_generic_to_shared(p);
}

#define CP_ASYNC16(sa, g) \
    asm volatile("cp.async.cg.shared.global [%0], [%1], 16;" :: "r"(sa), "l"(g) : "memory")
#define CP_COMMIT() asm volatile("cp.async.commit_group;" ::: "memory")
#define CP_WAIT0()  asm volatile("cp.async.wait_group 0;" ::: "memory")
#define CP_WAIT1()  asm volatile("cp.async.wait_group 1;" ::: "memory")

__device__ __forceinline__ uint32_t pkh(float a, float b) {
    __half2 h = __floats2half2_rn(a, b);
    return *(uint32_t*)&h;
}

// FMA-pipe exp (avoids MUFU throughput ceiling). rel err ~2e-6.
__device__ __forceinline__ float fast_exp(float x) {
    float t = x * 1.4426950408889634f;
    t = fmaxf(t, -120.0f);
    const int  ei = __float2int_rn(t);
    const float f = t - (float)ei;
    float p =        1.3333558146e-3f;
    p = fmaf(p, f,   9.6181291076e-3f);
    p = fmaf(p, f,   5.5504108664e-2f);
    p = fmaf(p, f,   2.4022650695e-1f);
    p = fmaf(p, f,   6.9314718056e-1f);
    p = fmaf(p, f,   1.0f);
    return p * __int_as_float((ei + 127) << 23);
}

// ---------------------------------------------------------------------------
// hs -> half.  grid 6144, block 256 (4 floats/thread)
// ---------------------------------------------------------------------------
__global__ __launch_bounds__(256) void hs_convert_kernel(
    const float* __restrict__ hs, __half* __restrict__ outh)
{
    const int i = (blockIdx.x * 256 + threadIdx.x) * 4;
    const float4 v = *(const float4*)(hs + i);
    *(uint2*)(outh + i) = make_uint2(pkh(v.x, v.y), pkh(v.z, v.w));
}

// ---------------------------------------------------------------------------
// W -> half, layout preserved [k][n]. grid (576, 12), block 256.
// ---------------------------------------------------------------------------
__global__ __launch_bounds__(256) void w_convert_kernel(
    const float* __restrict__ qw, const float* __restrict__ kw,
    const float* __restrict__ vw, __half* __restrict__ wh)
{
    const int which = blockIdx.y >> 2, g = blockIdx.y & 3;
    const float* W = (which == 0 ? qw : which == 1 ? kw : vw) + (size_t)g * NC * NC;
    __half* WH = wh + (size_t)blockIdx.y * NC * NC;
    const int i = (blockIdx.x * 256 + threadIdx.x) * 4;
    const float4 v = *(const float4*)(W + i);
    *(uint2*)(WH + i) = make_uint2(pkh(v.x, v.y), pkh(v.z, v.w));
}

// ---------------------------------------------------------------------------
// fp16 mma.sync QKV projection. 128x128 CTA tile, 8 warps (64x32 each),
// K in 12 chunks of 64. cp.async 3-STAGE ring, 1 __syncthreads per chunk.
// A frags via ldmatrix.x4, B frags via paired ldmatrix.x4.trans. 2 CTAs/SM.
// grid = (6, 16, 12), block = 256. Output q/k/v as half.
// ---------------------------------------------------------------------------
#define ASTR 36               // u32 stride per 64-half A row
#define ABUF (128*ASTR)       // 4608 u32
#define BSTR 68               // u32 stride per 128-half B row (+pad)
#define BBUF (64*BSTR)        // 4352 u32
#define QSTG (ABUF + BBUF)    // 8960 u32 per ring stage
#define QSMEM_U32 (3*QSTG)    // 26880 u32 = 107520 B

__global__ __launch_bounds__(256, 2) void qkv_h_kernel(
    const __half* __restrict__ hsh, const __half* __restrict__ wh,
    const float* __restrict__ qb, const float* __restrict__ kb, const float* __restrict__ vb,
    __half* __restrict__ qp, __half* __restrict__ kp, __half* __restrict__ vp)
{
    extern __shared__ uint32_t smu[];

    const int which = blockIdx.z >> 2, g = blockIdx.z & 3;
    const int m0 = blockIdx.y * 128, n0 = blockIdx.x * 128;
    const int tid = threadIdx.x, lane = tid & 31, wid = tid >> 5;
    const int wm = wid & 1, wn = wid >> 1;
    const int gq = lane >> 2, tg = lane & 3;

    const __half* Ag = hsh + (size_t)g * MPG * NC + (size_t)m0 * NC;
    const __half* Bg = wh + (size_t)(which * 4 + g) * NC * NC + n0;  // [k][n]
    const float*  bg = (which == 0 ? qb : which == 1 ? kb : vb) + (size_t)g * NC;
    __half*       op = (which == 0 ? qp : which == 1 ? kp : vp);

    float acc[4][4][4];
    #pragma unroll
    for (int i = 0; i < 4; i++)
        #pragma unroll
        for (int j = 0; j < 4; j++)
            #pragma unroll
            for (int q = 0; q < 4; q++) acc[i][j][q] = 0.f;

    const int alr = tid >> 1;          // A: 0..127 row
    const int alp = (tid & 1) * 32;    // A: half-offset within 64-half row
    const int blr = tid >> 2;          // B: 0..63 k-row
    const int blj = (tid & 3) * 4;     // B: uint4 group base

    // fragment lane mappings
    const int arow = (lane & 7) + ((lane >> 3) & 1) * 8;  // A ldmx4
    const int acol = ((lane >> 4) & 1) * 4;
    const int btrow = ((lane >> 3) & 1) * 8 + (lane & 7); // B ldmx4t row part
    const int btsel = ((lane >> 4) & 1) * 4;              // B ldmx4t col part

    // prologue: chunks 0,1 -> stages 0,1 (separate commit groups)
    #pragma unroll
    for (int pc = 0; pc < 2; pc++) {
        uint32_t* As = smu + pc * QSTG;
        uint32_t* Bs = As + ABUF;
        const int kc = pc * 64;
        #pragma unroll
        for (int j = 0; j < 4; j++) {
            CP_ASYNC16(cvta_s(As + alr * ASTR + alp / 2 + j * 4),
                       Ag + (size_t)alr * NC + kc + alp + j * 8);
            CP_ASYNC16(cvta_s(Bs + blr * BSTR + (blj + j) * 4),
                       Bg + (size_t)(kc + blr) * NC + (blj + j) * 8);
        }
        CP_COMMIT();
    }

    const int NCH = NC / 64;      // 12
    for (int c = 0; c < NCH; c++) {
        if (c + 1 < NCH) { CP_WAIT1(); } else { CP_WAIT0(); }
        __syncthreads();           // chunk c resident in stage c%3

        if (c + 2 < NCH) {         // prefetch c+2 into stage (c+2)%3
            uint32_t* As = smu + ((c + 2) % 3) * QSTG;
            uint32_t* Bs = As + ABUF;
            const int kc = (c + 2) * 64;
            #pragma unroll
            for (int j = 0; j < 4; j++) {
                CP_ASYNC16(cvta_s(As + alr * ASTR + alp / 2 + j * 4),
                           Ag + (size_t)alr * NC + kc + alp + j * 8);
                CP_ASYNC16(cvta_s(Bs + blr * BSTR + (blj + j) * 4),
                           Bg + (size_t)(kc + blr) * NC + (blj + j) * 8);
            }
            CP_COMMIT();
        }

        // compute chunk c: 4 k16-steps x 4 mt x 4 nt mma
        {
            const uint32_t* Ab = smu + (c % 3) * QSTG + (wm * 64) * ASTR;
            const uint32_t* Bb = smu + (c % 3) * QSTG + ABUF;
            #pragma unroll
            for (int kt = 0; kt < 4; kt++) {
                const int kk = kt * 8;
                uint32_t af[4][4], bf[4][2];
                #pragma unroll
                for (int mt = 0; mt < 4; mt++)
                    ldmx4(af[mt], cvta_s(Ab + (mt * 16 + arow) * ASTR + kk + acol));
                #pragma unroll
                for (int nt = 0; nt < 4; nt += 2) {
                    uint32_t t[4];
                    ldmx4t(t, cvta_s(Bb + (kt * 16 + btrow) * BSTR
                                     + wn * 16 + nt * 4 + btsel));
                    bf[nt][0] = t[0]; bf[nt][1] = t[1];
                    bf[nt + 1][0] = t[2]; bf[nt + 1][1] = t[3];
                }
                #pragma unroll
                for (int mt = 0; mt < 4; mt++)
                    #pragma unroll
                    for (int nt = 0; nt < 4; nt++)
                        mma_f16(acc[mt][nt], af[mt], bf[nt]);
            }
        }
    }

    // epilogue: bias add, pack to half, head-major scatter
    #pragma unroll
    for (int mt = 0; mt < 4; mt++) {
        const int row0 = m0 + wm * 64 + mt * 16 + gq;
        #pragma unroll
        for (int half_ = 0; half_ < 2; half_++) {
            const int trow = row0 + half_ * 8;
            const int b = trow >> 9, l = trow & 511;
            #pragma unroll
            for (int nt = 0; nt < 4; nt++) {
                const int col = n0 + wn * 32 + nt * 8 + 2 * tg;
                const int h = col >> 6, dh = col & 63;
                const float2 bv = *(const float2*)(bg + col);
                const uint32_t o = pkh(acc[mt][nt][half_ * 2 + 0] + bv.x,
                                       acc[mt][nt][half_ * 2 + 1] + bv.y);
                *(uint32_t*)(op + ((((size_t)g * NB + b) * NH + h) * LQ + l) * DH + dh) = o;
            }
        }
    }
}

// ---------------------------------------------------------------------------
// Online-softmax flash attention, fp16 mma.sync, 256 threads (8 warps).
// One CTA per (gbh, 128 queries). Warp w owns query rows [w*16, w*16+16).
// KV streamed in 8 chunks of 64 keys via cp.async 3-stage ring; 1 sync/chunk.
// K frags via ldmatrix.x2; V frags via ldmatrix.x2.trans (R14 form).
// smem (u32): Q[128][36] | mask[512]f | 3 x (K[64][36] + V[64][36])
// ---------------------------------------------------------------------------
#define FQT  128
#define FSP  36                       // u32 stride per 64-half row
#define FO_Q   0
#define FO_MSK (FQT*FSP)              // 4608
#define FO_KV  (FO_MSK + 512)         // 5120
#define FKV_B  (2*64*FSP)             // 4608 u32 per ring buffer (K then V)
#define FASM_U32 (FO_KV + 3*FKV_B)    // 18944 u32 = 75776 B

__global__ __launch_bounds__(256, 2) void attn_flash_kernel(
    const __half* __restrict__ qg, const __half* __restrict__ kg,
    const __half* __restrict__ vg, const float* __restrict__ mask,
    float* __restrict__ out)
{
    extern __shared__ uint32_t smu[];
    uint32_t* Qs  = smu + FO_Q;
    float*    Msk = (float*)(smu + FO_MSK);
    uint32_t* KVr = smu + FO_KV;

    const int gbh = blockIdx.y;
    const int l0q = blockIdx.x * FQT;
    const int h   = gbh % NH;
    const int gb  = gbh / NH;
    const int tid  = threadIdx.x;
    const int lane = tid & 31;
    const int wid  = tid >> 5;          // 0..7
    const int gq = lane >> 2, tg = lane & 3;

    const __half* Q  = qg + (size_t)gbh * LQ * DH + (size_t)l0q * DH;
    const __half* K  = kg + (size_t)gbh * LQ * DH;
    const __half* V  = vg + (size_t)gbh * LQ * DH;
    const float*  mk = mask + (size_t)gb * LQ;

    // ---- stage Q tile + mask ----
    #pragma unroll
    for (int i = 0; i < 4; i++) {
        const int idx = i * 256 + tid;
        const int r = idx >> 3, j = idx & 7;
        *(uint4*)(Qs + r * FSP + j * 4) =
            *(const uint4*)(Q + (size_t)r * DH + j * 8);
    }
    Msk[tid] = mk[tid];
    Msk[tid + 256] = mk[tid + 256];

    // ---- cp.async prologue: chunks 0,1 -> buffers 0,1 ----
    const int clr = tid >> 2;
    const int clj = (tid & 3) * 2;
    #pragma unroll
    for (int pc = 0; pc < 2; pc++) {
        uint32_t* B = KVr + pc * FKV_B;
        #pragma unroll
        for (int j = 0; j < 2; j++) {
            CP_ASYNC16(cvta_s(B + clr * FSP + (clj + j) * 4),
                       K + (size_t)(pc * 64 + clr) * DH + (clj + j) * 8);
            CP_ASYNC16(cvta_s(B + 64 * FSP + clr * FSP + (clj + j) * 4),
                       V + (size_t)(pc * 64 + clr) * DH + (clj + j) * 8);
        }
        CP_COMMIT();
    }

    uint32_t qf[4][4];
    float ctx[8][4];
    #pragma unroll
    for (int ntd = 0; ntd < 8; ntd++)
        #pragma unroll
        for (int q = 0; q < 4; q++) ctx[ntd][q] = 0.f;
    float m0 = -1e30f, m1 = -1e30f, sl0 = 0.f, sl1 = 0.f;

    const float scale = 0.125f;
    const int qrow = (lane & 7) + ((lane >> 3) & 1) * 8;
    const int qcol = ((lane >> 4) & 1) * 4;
    const int krow = lane & 7;
    const int kcol = ((lane >> 3) & 1) * 4;
    bool qf_loaded = false;

    for (int c = 0; c < 8; c++) {
        if (c < 7) { CP_WAIT1(); } else { CP_WAIT0(); }
        __syncthreads();                    // chunk c resident in buf c%3

        if (c + 2 < 8) {
            uint32_t* B = KVr + ((c + 2) % 3) * FKV_B;
            #pragma unroll
            for (int j = 0; j < 2; j++) {
                CP_ASYNC16(cvta_s(B + clr * FSP + (clj + j) * 4),
                           K + (size_t)((c + 2) * 64 + clr) * DH + (clj + j) * 8);
                CP_ASYNC16(cvta_s(B + 64 * FSP + clr * FSP + (clj + j) * 4),
                           V + (size_t)((c + 2) * 64 + clr) * DH + (clj + j) * 8);
            }
            CP_COMMIT();
        }

        if (!qf_loaded) {
            #pragma unroll
            for (int ks = 0; ks < 4; ks++)
                ldmx4(qf[ks], cvta_s(Qs + (wid * 16 + qrow) * FSP + ks * 8 + qcol));
            qf_loaded = true;
        }

        const uint32_t* Kb = KVr + (c % 3) * FKV_B;
        const uint32_t* Vb = Kb + 64 * FSP;

        // ---- QK^T: 16 queries x 64 keys ----
        float s[8][4];
        #pragma unroll
        for (int nt = 0; nt < 8; nt++)
            #pragma unroll
            for (int q = 0; q < 4; q++) s[nt][q] = 0.f;
        #pragma unroll
        for (int ks = 0; ks < 4; ks++)
            #pragma unroll
            for (int nt = 0; nt < 8; nt++) {
                uint32_t bf[2];
                ldmx2(bf[0], bf[1],
                      cvta_s(Kb + (nt * 8 + krow) * FSP + ks * 8 + kcol));
                mma_f16(s[nt], qf[ks], bf);
            }

        // ---- scale + mask + chunk row max ----
        float cm0 = -1e30f, cm1 = -1e30f;
        #pragma unroll
        for (int nt = 0; nt < 8; nt++) {
            const int col = c * 64 + nt * 8 + 2 * tg;
            const float mv0 = Msk[col], mv1 = Msk[col + 1];
            s[nt][0] = fmaf(s[nt][0], scale, mv0);
            s[nt][1] = fmaf(s[nt][1], scale, mv1);
            s[nt][2] = fmaf(s[nt][2], scale, mv0);
            s[nt][3] = fmaf(s[nt][3], scale, mv1);
            cm0 = fmaxf(cm0, fmaxf(s[nt][0], s[nt][1]));
            cm1 = fmaxf(cm1, fmaxf(s[nt][2], s[nt][3]));
        }
        cm0 = fmaxf(cm0, __shfl_xor_sync(0xFFFFFFFFu, cm0, 1));
        cm0 = fmaxf(cm0, __shfl_xor_sync(0xFFFFFFFFu, cm0, 2));
        cm1 = fmaxf(cm1, __shfl_xor_sync(0xFFFFFFFFu, cm1, 1));
        cm1 = fmaxf(cm1, __shfl_xor_sync(0xFFFFFFFFu, cm1, 2));

        // ---- online rescale ----
        const float nm0 = fmaxf(m0, cm0), nm1 = fmaxf(m1, cm1);
        const float f0 = fast_exp(m0 - nm0), f1 = fast_exp(m1 - nm1);
        m0 = nm0; m1 = nm1;

        // ---- exp -> packed half2 A-frags, chunk sums ----
        uint32_t ph[8][2];
        float cs0 = 0.f, cs1 = 0.f;
        #pragma unroll
        for (int nt = 0; nt < 8; nt++) {
            const float e0 = fast_exp(s[nt][0] - nm0);
            const float e1 = fast_exp(s[nt][1] - nm0);
            const float e2 = fast_exp(s[nt][2] - nm1);
            const float e3 = fast_exp(s[nt][3] - nm1);
            cs0 += e0 + e1;
            cs1 += e2 + e3;
            ph[nt][0] = pkh(e0, e1);
            ph[nt][1] = pkh(e2, e3);
        }
        cs0 += __shfl_xor_sync(0xFFFFFFFFu, cs0, 1);
        cs0 += __shfl_xor_sync(0xFFFFFFFFu, cs0, 2);
        cs1 += __shfl_xor_sync(0xFFFFFFFFu, cs1, 1);
        cs1 += __shfl_xor_sync(0xFFFFFFFFu, cs1, 2);
        sl0 = sl0 * f0 + cs0;
        sl1 = sl1 * f1 + cs1;

        #pragma unroll
        for (int ntd = 0; ntd < 8; ntd++) {
            ctx[ntd][0] *= f0; ctx[ntd][1] *= f0;
            ctx[ntd][2] *= f1; ctx[ntd][3] *= f1;
        }

        // ---- PV: P(16x64) @ V(64x64) ----
        #pragma unroll
        for (int kt = 0; kt < 4; kt++) {
            uint32_t av[4];
            av[0] = ph[2 * kt][0];
            av[1] = ph[2 * kt][1];
            av[2] = ph[2 * kt + 1][0];
            av[3] = ph[2 * kt + 1][1];
            const uint32_t* vp0 = Vb + (kt * 16 + (lane & 15)) * FSP;
            #pragma unroll
            for (int ntd = 0; ntd < 8; ntd++) {
                uint32_t bf[2];
                ldmx2t(bf[0], bf[1], cvta_s(vp0 + ntd * 4));
                mma_f16(ctx[ntd], av, bf);
            }
        }
    }

    // ---- epilogue: normalize, write out ----
    const float iv0 = 1.0f / sl0, iv1 = 1.0f / sl1;
    const size_t row0 = (size_t)gb * LQ + l0q + wid * 16 + gq;
    const int colo = h * DH + 2 * tg;
    #pragma unroll
    for (int ntd = 0; ntd < 8; ntd++) {
        *(float2*)(out + row0 * NC + colo + ntd * 8) =
            make_float2(ctx[ntd][0] * iv0, ctx[ntd][1] * iv0);
        *(float2*)(out + (row0 + 8) * NC + colo + ntd * 8) =
            make_float2(ctx[ntd][2] * iv1, ctx[ntd][3] * iv1);
    }
}

// ---------------------------------------------------------------------------
extern "C" void kernel_launch(void* const* d_in, const int* in_sizes, int n_in,
                              void* d_out, int out_size)
{
    (void)in_sizes; (void)n_in; (void)out_size;
    const float* hs   = (const float*)d_in[0];
    const float* mask = (const float*)d_in[1];
    const float* qw   = (const float*)d_in[2];
    const float* qb   = (const float*)d_in[3];
    const float* kw   = (const float*)d_in[4];
    const float* kb   = (const float*)d_in[5];
    const float* vw   = (const float*)d_in[6];
    const float* vb   = (const float*)d_in[7];
    float* out = (float*)d_out;

    void *qp, *kp, *vp, *wp, *hsp;
    cudaGetSymbolAddress(&qp, g_qh);
    cudaGetSymbolAddress(&kp, g_kh);
    cudaGetSymbolAddress(&vp, g_vh);
    cudaGetSymbolAddress(&wp, g_wh);
    cudaGetSymbolAddress(&hsp, g_hsh);

    hs_convert_kernel<<<NG * MPG * NC / 1024, 256>>>(hs, (__half*)hsp);

    dim3 wgrid(NC * NC / 1024, 12);
    w_convert_kernel<<<wgrid, 256>>>(qw, kw, vw, (__half*)wp);

    const int gsmem = QSMEM_U32 * (int)sizeof(uint32_t);  // 107520
    cudaFuncSetAttribute(qkv_h_kernel,
                         cudaFuncAttributeMaxDynamicSharedMemorySize, gsmem);
    dim3 ggrid(NC / 128, MPG / 128, 12);
    qkv_h_kernel<<<ggrid, 256, gsmem>>>((const __half*)hsp, (const __half*)wp,
                                        qb, kb, vb,
                                        (__half*)qp, (__half*)kp, (__half*)vp);

    const int asmem = FASM_U32 * (int)sizeof(uint32_t);   // 75776
    cudaFuncSetAttribute(attn_flash_kernel,
                         cudaFuncAttributeMaxDynamicSharedMemorySize, asmem);
    dim3 agrid(LQ / FQT, NG * NB * NH);
    attn_flash_kernel<<<agrid, 256, asmem>>>((const __half*)qp, (const __half*)kp,
                                             (const __half*)vp, mask, out);
}